// round 1
// baseline (speedup 1.0000x reference)
#include <cuda_runtime.h>

#define T_STEPS 2048
#define HV 32
#define HKC 16
#define DHEAD 64
#define CONV_DIM_C 4096
#define KEY_DIM_C 1024

// ---- scratch (static __device__, no allocation) ----
__device__ float  g_qn[T_STEPS * HKC * DHEAD];   // normalized q, 16 heads
__device__ float  g_kn[T_STEPS * HKC * DHEAD];   // normalized k, 16 heads
__device__ float  g_v [T_STEPS * HV * DHEAD];    // v, 32 heads
__device__ float2 g_gb[T_STEPS * HV];            // {exp(g), beta} per (t, head)

// ---------------------------------------------------------------------------
// Kernel 1: causal conv1d (K=4) + silu + split + l2norm(q,k) (+ q scale)
// grid = T rows, 512 threads, each thread handles 8 consecutive channels.
// ---------------------------------------------------------------------------
__global__ __launch_bounds__(512) void conv_kernel(
    const float* __restrict__ x,       // [T, 4096]
    const float* __restrict__ cstate,  // [1, 3, 4096] (zeros, but honored)
    const float* __restrict__ wgt)     // [4096, 4]
{
    const int t  = blockIdx.x;
    const int tid = threadIdx.x;
    const int d0 = tid * 8;

    float4 w[8];
#pragma unroll
    for (int j = 0; j < 8; j++) w[j] = ((const float4*)wgt)[d0 + j];

    float acc[8];
#pragma unroll
    for (int j = 0; j < 8; j++) acc[j] = 0.f;

#pragma unroll
    for (int wi = 0; wi < 4; wi++) {
        const int r = t - 3 + wi;
        const float* src = (r >= 0) ? (x + (size_t)r * CONV_DIM_C + d0)
                                    : (cstate + (size_t)(r + 3) * CONV_DIM_C + d0);
        float4 xa = *(const float4*)src;
        float4 xb = *(const float4*)(src + 4);
        float xv[8] = {xa.x, xa.y, xa.z, xa.w, xb.x, xb.y, xb.z, xb.w};
#pragma unroll
        for (int j = 0; j < 8; j++) {
            float ww = (wi == 0) ? w[j].x : (wi == 1) ? w[j].y : (wi == 2) ? w[j].z : w[j].w;
            acc[j] = fmaf(xv[j], ww, acc[j]);
        }
    }
    // silu
#pragma unroll
    for (int j = 0; j < 8; j++) {
        float s = acc[j];
        acc[j] = s / (1.f + __expf(-s));
    }

    if (d0 < 2 * KEY_DIM_C) {
        // q or k head group of 64 = 8 consecutive lanes (tid%8 aligned)
        float ss = 0.f;
#pragma unroll
        for (int j = 0; j < 8; j++) ss = fmaf(acc[j], acc[j], ss);
        ss += __shfl_xor_sync(0xffffffffu, ss, 1);
        ss += __shfl_xor_sync(0xffffffffu, ss, 2);
        ss += __shfl_xor_sync(0xffffffffu, ss, 4);
        float sc = rsqrtf(ss + 1e-6f);
        float* dst;
        if (d0 < KEY_DIM_C) { sc *= 0.125f; dst = g_qn + (size_t)t * 1024 + d0; }
        else                { dst = g_kn + (size_t)t * 1024 + (d0 - KEY_DIM_C); }
        float4 o0 = make_float4(acc[0]*sc, acc[1]*sc, acc[2]*sc, acc[3]*sc);
        float4 o1 = make_float4(acc[4]*sc, acc[5]*sc, acc[6]*sc, acc[7]*sc);
        *(float4*)dst       = o0;
        *(float4*)(dst + 4) = o1;
    } else {
        float* dst = g_v + (size_t)t * 2048 + (d0 - 2048);
        float4 o0 = make_float4(acc[0], acc[1], acc[2], acc[3]);
        float4 o1 = make_float4(acc[4], acc[5], acc[6], acc[7]);
        *(float4*)dst       = o0;
        *(float4*)(dst + 4) = o1;
    }
}

// ---------------------------------------------------------------------------
// Kernel 2: gates — precompute decay = exp(-exp(A_log)*softplus(a+dt_bias)),
// beta = sigmoid(b)
// ---------------------------------------------------------------------------
__global__ void gates_kernel(
    const float* __restrict__ b, const float* __restrict__ a,
    const float* __restrict__ alog, const float* __restrict__ dtb)
{
    int i = blockIdx.x * blockDim.x + threadIdx.x;
    if (i >= T_STEPS * HV) return;
    int h = i & 31;
    float beta = 1.f / (1.f + expf(-b[i]));
    float xx = a[i] + dtb[h];
    float sp = (xx > 20.f) ? xx : log1pf(expf(xx));
    float g = -expf(alog[h]) * sp;
    g_gb[i] = make_float2(expf(g), beta);
}

// ---------------------------------------------------------------------------
// Kernel 3: gated delta-rule recurrence.
// Each v-column of S is independent. Decomposition:
//   grid = 32 heads x 4 vblocks = 128 CTAs; 128 threads/CTA.
//   thread = (column within vblock, k-lane of 8); each lane owns 8 k-slots.
//   kv/o dot-products: per-lane partial + 3-level shfl.bfly over the 8-lane
//   segment. o-reduction of step t-1 is pipelined into step t.
// ---------------------------------------------------------------------------
__global__ __launch_bounds__(128) void recur_kernel(
    const float* __restrict__ S0in,   // [32, 64, 64] initial state
    float* __restrict__ out)          // [T, 32, 64]
{
    const int h   = blockIdx.x >> 2;
    const int vb  = blockIdx.x & 3;
    const int tid = threadIdx.x;
    const int col = vb * 16 + (tid >> 3);   // 0..63 (v-column)
    const int kl  = tid & 7;                // k-lane
    const int kb  = kl * 8;                 // first k-index owned

    const float*  kp = g_kn + ((h >> 1) * DHEAD + kb);
    const float*  qp = g_qn + ((h >> 1) * DHEAD + kb);
    const float*  vp = g_v  + (h * DHEAD + col);
    const float2* gp = g_gb + h;
    float*        op = out  + (h * DHEAD + col);

    float S[8];
#pragma unroll
    for (int j = 0; j < 8; j++)
        S[j] = S0in[(size_t)h * 4096 + (size_t)(kb + j) * 64 + col];

    // prefetch step 0
    float4 ka  = *(const float4*)kp;
    float4 kb4 = *(const float4*)(kp + 4);
    float4 qa  = *(const float4*)qp;
    float4 qb4 = *(const float4*)(qp + 4);
    float  vv  = *vp;
    float2 gb  = *gp;

    float opart = 0.f;

    for (int t = 0; t < T_STEPS; ++t) {
        const float k0=ka.x, k1=ka.y, k2=ka.z, k3=ka.w;
        const float k4=kb4.x,k5=kb4.y,k6=kb4.z,k7=kb4.w;
        const float q0=qa.x, q1=qa.y, q2=qa.z, q3=qa.w;
        const float q4=qb4.x,q5=qb4.y,q6=qb4.z,q7=qb4.w;
        const float dec = gb.x, bet = gb.y, vcur = vv;

        // prefetch next step's streams (hide L2/DRAM latency under compute)
        if (t + 1 < T_STEPS) {
            kp += 1024; qp += 1024; vp += 2048; gp += 32;
            ka  = *(const float4*)kp;  kb4 = *(const float4*)(kp + 4);
            qa  = *(const float4*)qp;  qb4 = *(const float4*)(qp + 4);
            vv  = *vp;                 gb  = *gp;
        }

        // kv partial dot against OLD state (decay folded in after reduce)
        float kva = S[0]*k0; kva = fmaf(S[1],k1,kva); kva = fmaf(S[2],k2,kva); kva = fmaf(S[3],k3,kva);
        float kvb = S[4]*k4; kvb = fmaf(S[5],k5,kvb); kvb = fmaf(S[6],k6,kvb); kvb = fmaf(S[7],k7,kvb);
        float kv = kva + kvb;

        // pipelined: finish + store previous step's output (independent chain)
        opart += __shfl_xor_sync(0xffffffffu, opart, 1);
        opart += __shfl_xor_sync(0xffffffffu, opart, 2);
        opart += __shfl_xor_sync(0xffffffffu, opart, 4);
        if (t > 0 && kl == 0) op[(size_t)(t - 1) * 2048] = opart;

        // kv reduce over the 8-lane segment
        kv += __shfl_xor_sync(0xffffffffu, kv, 1);
        kv += __shfl_xor_sync(0xffffffffu, kv, 2);
        kv += __shfl_xor_sync(0xffffffffu, kv, 4);

        const float u = bet * fmaf(-dec, kv, vcur);   // beta*(v - dec*kv)

        float oa, ob;
        S[0] = fmaf(dec, S[0], k0*u); oa = S[0]*q0;
        S[1] = fmaf(dec, S[1], k1*u); oa = fmaf(S[1], q1, oa);
        S[2] = fmaf(dec, S[2], k2*u); oa = fmaf(S[2], q2, oa);
        S[3] = fmaf(dec, S[3], k3*u); oa = fmaf(S[3], q3, oa);
        S[4] = fmaf(dec, S[4], k4*u); ob = S[4]*q4;
        S[5] = fmaf(dec, S[5], k5*u); ob = fmaf(S[5], q5, ob);
        S[6] = fmaf(dec, S[6], k6*u); ob = fmaf(S[6], q6, ob);
        S[7] = fmaf(dec, S[7], k7*u); ob = fmaf(S[7], q7, ob);
        opart = oa + ob;
    }

    // epilogue: last step's output
    opart += __shfl_xor_sync(0xffffffffu, opart, 1);
    opart += __shfl_xor_sync(0xffffffffu, opart, 2);
    opart += __shfl_xor_sync(0xffffffffu, opart, 4);
    if (kl == 0) op[(size_t)(T_STEPS - 1) * 2048] = opart;
}

// ---------------------------------------------------------------------------
extern "C" void kernel_launch(void* const* d_in, const int* in_sizes, int n_in,
                              void* d_out, int out_size)
{
    const float* x    = (const float*)d_in[0];  // mixed_qkv [2048, 4096]
    const float* cs   = (const float*)d_in[1];  // conv_state_in [1,3,4096]
    const float* s0   = (const float*)d_in[2];  // recurrent_state_in [1,32,64,64]
    const float* b    = (const float*)d_in[3];  // [2048, 32]
    const float* a    = (const float*)d_in[4];  // [2048, 32]
    const float* w    = (const float*)d_in[5];  // conv1d_weight [4096, 4]
    const float* alog = (const float*)d_in[6];  // [32]
    const float* dtb  = (const float*)d_in[7];  // [32]

    conv_kernel<<<T_STEPS, 512>>>(x, cs, w);
    gates_kernel<<<(T_STEPS * HV + 255) / 256, 256>>>(b, a, alog, dtb);
    recur_kernel<<<128, 128>>>(s0, (float*)d_out);
}

// round 2
// speedup vs baseline: 1.6364x; 1.6364x over previous
#include <cuda_runtime.h>

#define T_STEPS 2048
#define HV 32
#define HKC 16
#define DHEAD 64
#define CONV_DIM_C 4096
#define KEY_DIM_C 1024
#define NCHUNK 32
#define CLEN 64
#define SP 68     // smem row stride (floats) for 64-wide matrices, chunk kernel
#define SQ2 66    // smem row stride, seq kernel

// ---- scratch (static __device__, no allocation) ----
__device__ float g_qn[T_STEPS * HKC * DHEAD];   // normalized*scaled q, 16 heads
__device__ float g_kn[T_STEPS * HKC * DHEAD];   // normalized k, 16 heads
__device__ float g_v [T_STEPS * HV * DHEAD];    // v, 32 heads
__device__ float g_g   [T_STEPS * HV];          // raw log-decay g per (t,h)
__device__ float g_beta[T_STEPS * HV];          // sigmoid(b)
// per (chunk, head) precomputed matrices [NCHUNK][HV][64*64]
__device__ float g_Qeff[NCHUNK * HV * 4096];
__device__ float g_G   [NCHUNK * HV * 4096];
__device__ float g_H   [NCHUNK * HV * 4096];

// ---------------------------------------------------------------------------
// Kernel 1: causal conv1d (K=4) + silu + split + l2norm(q,k) (+ q scale)
// ---------------------------------------------------------------------------
__global__ __launch_bounds__(512) void conv_kernel(
    const float* __restrict__ x,
    const float* __restrict__ cstate,
    const float* __restrict__ wgt)
{
    const int t  = blockIdx.x;
    const int tid = threadIdx.x;
    const int d0 = tid * 8;

    float4 w[8];
#pragma unroll
    for (int j = 0; j < 8; j++) w[j] = ((const float4*)wgt)[d0 + j];

    float acc[8];
#pragma unroll
    for (int j = 0; j < 8; j++) acc[j] = 0.f;

#pragma unroll
    for (int wi = 0; wi < 4; wi++) {
        const int r = t - 3 + wi;
        const float* src = (r >= 0) ? (x + (size_t)r * CONV_DIM_C + d0)
                                    : (cstate + (size_t)(r + 3) * CONV_DIM_C + d0);
        float4 xa = *(const float4*)src;
        float4 xb = *(const float4*)(src + 4);
        float xv[8] = {xa.x, xa.y, xa.z, xa.w, xb.x, xb.y, xb.z, xb.w};
#pragma unroll
        for (int j = 0; j < 8; j++) {
            float ww = (wi == 0) ? w[j].x : (wi == 1) ? w[j].y : (wi == 2) ? w[j].z : w[j].w;
            acc[j] = fmaf(xv[j], ww, acc[j]);
        }
    }
#pragma unroll
    for (int j = 0; j < 8; j++) {
        float s = acc[j];
        acc[j] = s / (1.f + __expf(-s));
    }

    if (d0 < 2 * KEY_DIM_C) {
        float ss = 0.f;
#pragma unroll
        for (int j = 0; j < 8; j++) ss = fmaf(acc[j], acc[j], ss);
        ss += __shfl_xor_sync(0xffffffffu, ss, 1);
        ss += __shfl_xor_sync(0xffffffffu, ss, 2);
        ss += __shfl_xor_sync(0xffffffffu, ss, 4);
        float sc = rsqrtf(ss + 1e-6f);
        float* dst;
        if (d0 < KEY_DIM_C) { sc *= 0.125f; dst = g_qn + (size_t)t * 1024 + d0; }
        else                { dst = g_kn + (size_t)t * 1024 + (d0 - KEY_DIM_C); }
        *(float4*)dst       = make_float4(acc[0]*sc, acc[1]*sc, acc[2]*sc, acc[3]*sc);
        *(float4*)(dst + 4) = make_float4(acc[4]*sc, acc[5]*sc, acc[6]*sc, acc[7]*sc);
    } else {
        float* dst = g_v + (size_t)t * 2048 + (d0 - 2048);
        *(float4*)dst       = make_float4(acc[0], acc[1], acc[2], acc[3]);
        *(float4*)(dst + 4) = make_float4(acc[4], acc[5], acc[6], acc[7]);
    }
}

// ---------------------------------------------------------------------------
// Kernel 2: gates — g = -exp(A_log)*softplus(a+dt_bias), beta = sigmoid(b)
// ---------------------------------------------------------------------------
__global__ void gates_kernel(
    const float* __restrict__ b, const float* __restrict__ a,
    const float* __restrict__ alog, const float* __restrict__ dtb)
{
    int i = blockIdx.x * blockDim.x + threadIdx.x;
    if (i >= T_STEPS * HV) return;
    int h = i & 31;
    g_beta[i] = 1.f / (1.f + expf(-b[i]));
    float xx = a[i] + dtb[h];
    float sp = (xx > 20.f) ? xx : log1pf(expf(xx));
    g_g[i] = -expf(alog[h]) * sp;
}

// ---------------------------------------------------------------------------
// mm helper: acc[4][4] += sum_d X[(r0+ri)*SP+d] * Y[d*SP + c0+ci]
// ---------------------------------------------------------------------------
__device__ __forceinline__ void mm64(const float* __restrict__ X,
                                     const float* __restrict__ Y,
                                     int r0, int c0, float* __restrict__ acc)
{
#pragma unroll 8
    for (int d = 0; d < 64; d++) {
        float4 y = *(const float4*)(Y + d * SP + c0);
        float x0 = X[(r0 + 0) * SP + d];
        float x1 = X[(r0 + 1) * SP + d];
        float x2 = X[(r0 + 2) * SP + d];
        float x3 = X[(r0 + 3) * SP + d];
        acc[ 0] = fmaf(x0, y.x, acc[ 0]); acc[ 1] = fmaf(x0, y.y, acc[ 1]);
        acc[ 2] = fmaf(x0, y.z, acc[ 2]); acc[ 3] = fmaf(x0, y.w, acc[ 3]);
        acc[ 4] = fmaf(x1, y.x, acc[ 4]); acc[ 5] = fmaf(x1, y.y, acc[ 5]);
        acc[ 6] = fmaf(x1, y.z, acc[ 6]); acc[ 7] = fmaf(x1, y.w, acc[ 7]);
        acc[ 8] = fmaf(x2, y.x, acc[ 8]); acc[ 9] = fmaf(x2, y.y, acc[ 9]);
        acc[10] = fmaf(x2, y.z, acc[10]); acc[11] = fmaf(x2, y.w, acc[11]);
        acc[12] = fmaf(x3, y.x, acc[12]); acc[13] = fmaf(x3, y.y, acc[13]);
        acc[14] = fmaf(x3, y.z, acc[14]); acc[15] = fmaf(x3, y.w, acc[15]);
    }
}

// ---------------------------------------------------------------------------
// Kernel 3 (parallel over all chunks*heads): per-chunk WY-form precompute.
//   Outputs: Ointra -> d_out, Qeff/G/H -> global scratch.
// ---------------------------------------------------------------------------
__global__ __launch_bounds__(256) void chunk_kernel(float* __restrict__ out)
{
    extern __shared__ float sm[];
    float* sK   = sm;                 // [64][SP]
    float* sKT  = sK   + 64 * SP;     // [64][SP]  K transposed (later scaled)
    float* sQr  = sKT  + 64 * SP;     // [64][SP]  raw q (normalized+scaled)
    float* sVA  = sQr  + 64 * SP;     // [64][SP]  V, later Attn
    float* sM   = sVA  + 64 * SP;     // [64][SP]
    float* sW   = sM   + 64 * SP;     // [64][SP]
    float* sPp  = sW   + 64 * SP;     // [64][SP]
    float* scg  = sPp  + 64 * SP;     // [64] cumulative log-decay
    float* sE   = scg  + 64;          // [64] exp(cg)
    float* sBeta= sE   + 64;          // [64]
    float* sTmp = sBeta+ 64;          // [64]

    const int cid = blockIdx.x;
    const int i = cid >> 5;          // chunk
    const int h = cid & 31;          // v-head
    const int tid = threadIdx.x;
    const int ty = tid >> 4, tx = tid & 15;
    const int r0 = ty * 4, c0 = tx * 4;

    // ---- load K (+transpose), Q, V ----
    const float* Kg = g_kn + (size_t)(i * 64) * 1024 + (h >> 1) * 64;
    const float* Qg = g_qn + (size_t)(i * 64) * 1024 + (h >> 1) * 64;
    const float* Vg = g_v  + (size_t)(i * 64) * 2048 + h * 64;
    for (int idx = tid; idx < 64 * 16; idx += 256) {
        int r = idx >> 4, c4 = (idx & 15) << 2;
        float4 kv = *(const float4*)(Kg + (size_t)r * 1024 + c4);
        sK[r * SP + c4 + 0] = kv.x; sK[r * SP + c4 + 1] = kv.y;
        sK[r * SP + c4 + 2] = kv.z; sK[r * SP + c4 + 3] = kv.w;
        sKT[(c4 + 0) * SP + r] = kv.x; sKT[(c4 + 1) * SP + r] = kv.y;
        sKT[(c4 + 2) * SP + r] = kv.z; sKT[(c4 + 3) * SP + r] = kv.w;
        float4 qv = *(const float4*)(Qg + (size_t)r * 1024 + c4);
        sQr[r * SP + c4 + 0] = qv.x; sQr[r * SP + c4 + 1] = qv.y;
        sQr[r * SP + c4 + 2] = qv.z; sQr[r * SP + c4 + 3] = qv.w;
        float4 vv = *(const float4*)(Vg + (size_t)r * 2048 + c4);
        sVA[r * SP + c4 + 0] = vv.x; sVA[r * SP + c4 + 1] = vv.y;
        sVA[r * SP + c4 + 2] = vv.z; sVA[r * SP + c4 + 3] = vv.w;
    }
    if (tid < 64) {
        scg[tid]   = g_g   [(size_t)(i * 64 + tid) * 32 + h];
        sBeta[tid] = g_beta[(size_t)(i * 64 + tid) * 32 + h];
    }
    __syncthreads();

    // ---- inclusive scan of log-decay ----
#pragma unroll
    for (int off = 1; off < 64; off <<= 1) {
        float v = 0.f;
        if (tid < 64) v = scg[tid] + ((tid >= off) ? scg[tid - off] : 0.f);
        __syncthreads();
        if (tid < 64) scg[tid] = v;
        __syncthreads();
    }
    if (tid < 64) sE[tid] = __expf(scg[tid]);
    __syncthreads();

    float acc[16];

    // ---- (a) KK -> M ----
#pragma unroll
    for (int j = 0; j < 16; j++) acc[j] = 0.f;
    mm64(sK, sKT, r0, c0, acc);
#pragma unroll
    for (int ri = 0; ri < 4; ri++) {
        int t = r0 + ri;
        float bt = sBeta[t], ct = scg[t];
#pragma unroll
        for (int ci = 0; ci < 4; ci++) {
            int s = c0 + ci;
            sM[t * SP + s] = (s < t) ? bt * acc[ri * 4 + ci] * __expf(ct - scg[s]) : 0.f;
        }
    }
    __syncthreads();

    // ---- (c) forward substitution: (I+M)[W|P] = [beta*E*K | beta*V] ----
    {
        float* Xb = (tid < 64) ? (sW + tid) : (sPp + (tid - 64));
        for (int t = 0; t < 64; t++) {
            if (tid < 128) {
                float rhs = (tid < 64)
                    ? sBeta[t] * sE[t] * sK[t * SP + tid]
                    : sBeta[t] * sVA[t * SP + (tid - 64)];
                const float* Mr = sM + t * SP;
                float a0 = 0.f, a1 = 0.f, a2 = 0.f, a3 = 0.f;
                int s = 0;
                for (; s + 4 <= t; s += 4) {
                    a0 = fmaf(Mr[s + 0], Xb[(s + 0) * SP], a0);
                    a1 = fmaf(Mr[s + 1], Xb[(s + 1) * SP], a1);
                    a2 = fmaf(Mr[s + 2], Xb[(s + 2) * SP], a2);
                    a3 = fmaf(Mr[s + 3], Xb[(s + 3) * SP], a3);
                }
                for (; s < t; s++) a0 = fmaf(Mr[s], Xb[s * SP], a0);
                Xb[t * SP] = rhs - ((a0 + a1) + (a2 + a3));
            }
            __syncthreads();
        }
    }

    // ---- (d) QK -> Attn (into sVA) ----
#pragma unroll
    for (int j = 0; j < 16; j++) acc[j] = 0.f;
    mm64(sQr, sKT, r0, c0, acc);
    __syncthreads();   // everyone done reading sVA as V (solve already synced, but be safe)
#pragma unroll
    for (int ri = 0; ri < 4; ri++) {
        int t = r0 + ri;
        float ct = scg[t];
#pragma unroll
        for (int ci = 0; ci < 4; ci++) {
            int s = c0 + ci;
            sVA[t * SP + s] = (s <= t) ? acc[ri * 4 + ci] * __expf(ct - scg[s]) : 0.f;
        }
    }
    // ---- scale sKT columns: sKT[k][s] *= exp(cg63 - cg_s)  (builds Cbar^T) ----
    if (tid < 64) sTmp[tid] = __expf(scg[63] - scg[tid]);
    __syncthreads();
    for (int idx = tid; idx < 4096; idx += 256) {
        int k = idx >> 6, s = idx & 63;
        sKT[k * SP + s] *= sTmp[s];
    }
    __syncthreads();

    const size_t base = ((size_t)(i * 32 + h)) << 12;

    // ---- (e) Qeff = E*Q - Attn@W ----
#pragma unroll
    for (int j = 0; j < 16; j++) acc[j] = 0.f;
    mm64(sVA, sW, r0, c0, acc);
#pragma unroll
    for (int ri = 0; ri < 4; ri++) {
        int t = r0 + ri;
        float et = sE[t];
        float4 o;
        o.x = et * sQr[t * SP + c0 + 0] - acc[ri * 4 + 0];
        o.y = et * sQr[t * SP + c0 + 1] - acc[ri * 4 + 1];
        o.z = et * sQr[t * SP + c0 + 2] - acc[ri * 4 + 2];
        o.w = et * sQr[t * SP + c0 + 3] - acc[ri * 4 + 3];
        *(float4*)(g_Qeff + base + t * 64 + c0) = o;
    }

    // ---- (f) Ointra = Attn@P -> out ----
#pragma unroll
    for (int j = 0; j < 16; j++) acc[j] = 0.f;
    mm64(sVA, sPp, r0, c0, acc);
#pragma unroll
    for (int ri = 0; ri < 4; ri++) {
        int t = r0 + ri;
        float4 o = make_float4(acc[ri*4+0], acc[ri*4+1], acc[ri*4+2], acc[ri*4+3]);
        *(float4*)(out + (size_t)(i * 64 + t) * 2048 + h * 64 + c0) = o;
    }

    // ---- (g) G = B63*I - Cbar^T @ W ----
#pragma unroll
    for (int j = 0; j < 16; j++) acc[j] = 0.f;
    mm64(sKT, sW, r0, c0, acc);
    {
        float b63 = sE[63];
#pragma unroll
        for (int ri = 0; ri < 4; ri++) {
            int k = r0 + ri;
            float4 o;
            o.x = ((k == c0 + 0) ? b63 : 0.f) - acc[ri * 4 + 0];
            o.y = ((k == c0 + 1) ? b63 : 0.f) - acc[ri * 4 + 1];
            o.z = ((k == c0 + 2) ? b63 : 0.f) - acc[ri * 4 + 2];
            o.w = ((k == c0 + 3) ? b63 : 0.f) - acc[ri * 4 + 3];
            *(float4*)(g_G + base + k * 64 + c0) = o;
        }
    }

    // ---- (h) H = Cbar^T @ P ----
#pragma unroll
    for (int j = 0; j < 16; j++) acc[j] = 0.f;
    mm64(sKT, sPp, r0, c0, acc);
#pragma unroll
    for (int ri = 0; ri < 4; ri++) {
        int k = r0 + ri;
        float4 o = make_float4(acc[ri*4+0], acc[ri*4+1], acc[ri*4+2], acc[ri*4+3]);
        *(float4*)(g_H + base + k * 64 + c0) = o;
    }
}

// ---------------------------------------------------------------------------
// Kernel 4 (sequential over chunks, parallel over heads x v-blocks):
//   out[t][v] += Qeff_i[t][:] @ S[:, v];  S = G_i @ S + H_i
// ---------------------------------------------------------------------------
__global__ __launch_bounds__(256) void seq_kernel(
    const float* __restrict__ S0, float* __restrict__ out)
{
    __shared__ float sQe[64 * SQ2];
    __shared__ float sG [64 * SQ2];
    __shared__ float sSa[64 * 16];
    __shared__ float sSb[64 * 16];

    const int h  = blockIdx.x >> 2;
    const int vb = blockIdx.x & 3;
    const int tid = threadIdx.x;
    const int row = tid >> 2;        // t (O step) / k (S step)
    const int sub = tid & 3;
    const int vloc = sub * 4;
    const int vglob = vb * 16 + vloc;

    // init S columns
    {
        float4 s0 = *(const float4*)(S0 + (size_t)h * 4096 + row * 64 + vglob);
        *(float4*)(sSa + row * 16 + vloc) = s0;
    }
    __syncthreads();

    float* Scur = sSa;
    float* Snew = sSb;

    for (int i = 0; i < NCHUNK; i++) {
        const size_t base = ((size_t)(i * 32 + h)) << 12;
        const float* Qe = g_Qeff + base;
        const float* Gg = g_G + base;
        for (int idx = tid; idx < 1024; idx += 256) {
            int r = idx >> 4, c4 = (idx & 15) << 2;
            float4 aq = *(const float4*)(Qe + r * 64 + c4);
            sQe[r * SQ2 + c4 + 0] = aq.x; sQe[r * SQ2 + c4 + 1] = aq.y;
            sQe[r * SQ2 + c4 + 2] = aq.z; sQe[r * SQ2 + c4 + 3] = aq.w;
            float4 ag = *(const float4*)(Gg + r * 64 + c4);
            sG[r * SQ2 + c4 + 0] = ag.x; sG[r * SQ2 + c4 + 1] = ag.y;
            sG[r * SQ2 + c4 + 2] = ag.z; sG[r * SQ2 + c4 + 3] = ag.w;
        }
        __syncthreads();

        // O step: out[i*64+row][h][vglob..+3] += Qeff[row][:] @ Scur[:, v]
        {
            float a0 = 0.f, a1 = 0.f, a2 = 0.f, a3 = 0.f;
#pragma unroll 8
            for (int j = 0; j < 64; j++) {
                float q = sQe[row * SQ2 + j];
                float4 sv = *(const float4*)(Scur + j * 16 + vloc);
                a0 = fmaf(q, sv.x, a0); a1 = fmaf(q, sv.y, a1);
                a2 = fmaf(q, sv.z, a2); a3 = fmaf(q, sv.w, a3);
            }
            float* op = out + (size_t)(i * 64 + row) * 2048 + h * 64 + vglob;
            float4 o = *(const float4*)op;
            o.x += a0; o.y += a1; o.z += a2; o.w += a3;
            *(float4*)op = o;
        }

        // S step: Snew[row][v] = G[row][:] @ Scur[:, v] + H[row][v]
        {
            float4 hv = *(const float4*)(g_H + base + row * 64 + vglob);
            float a0 = hv.x, a1 = hv.y, a2 = hv.z, a3 = hv.w;
#pragma unroll 8
            for (int j = 0; j < 64; j++) {
                float gv = sG[row * SQ2 + j];
                float4 sv = *(const float4*)(Scur + j * 16 + vloc);
                a0 = fmaf(gv, sv.x, a0); a1 = fmaf(gv, sv.y, a1);
                a2 = fmaf(gv, sv.z, a2); a3 = fmaf(gv, sv.w, a3);
            }
            *(float4*)(Snew + row * 16 + vloc) = make_float4(a0, a1, a2, a3);
        }
        __syncthreads();
        float* tmp = Scur; Scur = Snew; Snew = tmp;
    }
}

// ---------------------------------------------------------------------------
extern "C" void kernel_launch(void* const* d_in, const int* in_sizes, int n_in,
                              void* d_out, int out_size)
{
    const float* x    = (const float*)d_in[0];
    const float* cs   = (const float*)d_in[1];
    const float* s0   = (const float*)d_in[2];
    const float* b    = (const float*)d_in[3];
    const float* a    = (const float*)d_in[4];
    const float* w    = (const float*)d_in[5];
    const float* alog = (const float*)d_in[6];
    const float* dtb  = (const float*)d_in[7];

    const int smem_bytes = (7 * 64 * SP + 256) * sizeof(float);  // ~122.9 KB
    cudaFuncSetAttribute(chunk_kernel,
                         cudaFuncAttributeMaxDynamicSharedMemorySize, smem_bytes);

    conv_kernel<<<T_STEPS, 512>>>(x, cs, w);
    gates_kernel<<<(T_STEPS * HV + 255) / 256, 256>>>(b, a, alog, dtb);
    chunk_kernel<<<NCHUNK * HV, 256, smem_bytes>>>((float*)d_out);
    seq_kernel<<<128, 256>>>(s0, (float*)d_out);
}